// round 13
// baseline (speedup 1.0000x reference)
#include <cuda_runtime.h>
#include <cuda_bf16.h>
#include <math.h>
#include <stdint.h>

#define Nn 4096
#define Ee 4096
#define NHID 512
#define NHEAD 8
#define DKh 64
#define NLAYER 4
#define NCLASS 16
#define CAP 128

// ---------------- scratch ----------------
__device__ float g_x[Nn * NHID];
__device__ float g_q[Nn * NHID];
__device__ float g_k[Nn * NHID];
__device__ float g_v[Nn * NHID];
__device__ float g_w[Ee * NHID];
__device__ float g_gv[Nn * NHID];
__device__ float g_ctx[Nn * NHID];
__device__ float g_pre[Nn * NHID];
__device__ float g_DV[Nn];
__device__ float g_DEpart[32 * Ee];
__device__ float g_dv2[Nn];
__device__ float g_invDE[Ee];
__device__ int   g_rowIdx[Nn * CAP];
__device__ int   g_rowCnt[Nn];
__device__ int   g_colIdx[Ee * CAP];
__device__ int   g_colCnt[Ee];
__device__ uint2 g_kc[(size_t)NHEAD * 32 * Nn];        // split-bf16 K: [h][d-pair][n]
__device__ uint2 g_vc[(size_t)NHEAD * (Nn / 2) * 64];  // split-bf16 V: [h][key-pair][d]

// ---------------- degrees ----------------
__global__ void row_sums_k(const float* __restrict__ H) {
    int t = threadIdx.x;
    const float* row = H + (size_t)blockIdx.x * Ee;
    float s = 0.f;
    for (int e = t; e < Ee; e += 256) s += row[e];
    __shared__ float red[256];
    red[t] = s; __syncthreads();
    for (int w = 128; w > 0; w >>= 1) { if (t < w) red[t] += red[t + w]; __syncthreads(); }
    if (t == 0) g_DV[blockIdx.x] = red[0];
}

__global__ void col_part_k(const float* __restrict__ H) {
    int e = blockIdx.x * 256 + threadIdx.x;
    int r0 = blockIdx.y * 128;
    float s = 0.f;
    for (int n = r0; n < r0 + 128; n++) s += H[(size_t)n * Ee + e];
    g_DEpart[blockIdx.y * Ee + e] = s;
}

__global__ void finalize_deg_k() {
    int i = blockIdx.x * 256 + threadIdx.x;
    if (i < Nn) g_dv2[i] = (i == 0) ? 1.0f : rsqrtf(g_DV[i]);
    if (i < Ee) {
        float s = 0.f;
        for (int p = 0; p < 32; p++) s += g_DEpart[p * Ee + i];
        g_invDE[i] = 1.0f / s;
    }
}

// ---------------- CSR build (deterministic) ----------------
__global__ void rowlist_k(const float* __restrict__ H) {
    int warp = threadIdx.x >> 5, lane = threadIdx.x & 31;
    int n = blockIdx.x * 8 + warp;
    const float* row = H + (size_t)n * Ee;
    int cnt = 0;
    for (int base = 0; base < Ee; base += 32) {
        float v = row[base + lane];
        unsigned mask = __ballot_sync(0xffffffffu, v != 0.f);
        int off = __popc(mask & ((1u << lane) - 1u));
        if (v != 0.f && cnt + off < CAP) g_rowIdx[n * CAP + cnt + off] = base + lane;
        cnt += __popc(mask);
    }
    if (lane == 0) g_rowCnt[n] = cnt < CAP ? cnt : CAP;
}

__global__ void collist_k(const float* __restrict__ H) {
    int e = blockIdx.x * 256 + threadIdx.x;
    int cnt = 0;
    for (int n = 0; n < Nn; n++) {
        if (H[(size_t)n * Ee + e] != 0.f) {
            if (cnt < CAP) g_colIdx[e * CAP + cnt] = n;
            cnt++;
        }
    }
    g_colCnt[e] = cnt < CAP ? cnt : CAP;
}

// ---------------- sparse gathers ----------------
__global__ void edge_gather_k(const float* __restrict__ v) {
    int e = blockIdx.x, t = threadIdx.x;   // 128 threads
    int cnt = g_colCnt[e];
    float inv = g_invDE[e];
    float4 acc = make_float4(0.f, 0.f, 0.f, 0.f);
    const int* lst = g_colIdx + e * CAP;
    for (int j = 0; j < cnt; j++) {
        int n = lst[j];
        float s = g_dv2[n];
        float4 x = *(const float4*)&v[(size_t)n * NHID + t * 4];
        acc.x += s * x.x; acc.y += s * x.y; acc.z += s * x.z; acc.w += s * x.w;
    }
    float4 r = make_float4(inv * acc.x, inv * acc.y, inv * acc.z, inv * acc.w);
    *(float4*)&g_w[(size_t)e * NHID + t * 4] = r;
}

__global__ void node_gather_k() {
    int n = blockIdx.x, t = threadIdx.x;   // 128 threads
    int cnt = g_rowCnt[n];
    float s = g_dv2[n];
    float4 acc = make_float4(0.f, 0.f, 0.f, 0.f);
    const int* lst = g_rowIdx + n * CAP;
    for (int j = 0; j < cnt; j++) {
        int e = lst[j];
        float4 x = *(const float4*)&g_w[(size_t)e * NHID + t * 4];
        acc.x += x.x; acc.y += x.y; acc.z += x.z; acc.w += x.w;
    }
    float4 r = make_float4(s * acc.x, s * acc.y, s * acc.z, s * acc.w);
    *(float4*)&g_gv[(size_t)n * NHID + t * 4] = r;
}

// ---------------- bf16 split helpers ----------------
__device__ __forceinline__ void split2(float x0, float x1, uint32_t& hi, uint32_t& lo) {
    uint32_t h;
    asm("cvt.rn.bf16x2.f32 %0, %1, %2;" : "=r"(h) : "f"(x1), "f"(x0));
    float h0 = __uint_as_float(h << 16);
    float h1 = __uint_as_float(h & 0xffff0000u);
    asm("cvt.rn.bf16x2.f32 %0, %1, %2;" : "=r"(lo) : "f"(x1 - h1), "f"(x0 - h0));
    hi = h;
}

__device__ __forceinline__ void mma_bf16(float c[4], uint32_t a0, uint32_t a1,
                                         uint32_t a2, uint32_t a3,
                                         uint32_t b0, uint32_t b1) {
    asm volatile(
        "mma.sync.aligned.m16n8k16.row.col.f32.bf16.bf16.f32 "
        "{%0,%1,%2,%3},{%4,%5,%6,%7},{%8,%9},{%0,%1,%2,%3};"
        : "+f"(c[0]), "+f"(c[1]), "+f"(c[2]), "+f"(c[3])
        : "r"(a0), "r"(a1), "r"(a2), "r"(a3), "r"(b0), "r"(b1));
}

// FMA-pipe exp for x <= 0. rel err ~1e-7.
__device__ __forceinline__ float fexp(float x) {
    float y = x * 1.44269504088896f;
    y = fmaxf(y, -126.f);
    float r = rintf(y);
    float f = y - r;
    float p = 1.5426461e-4f;
    p = fmaf(p, f, 1.3333558e-3f);
    p = fmaf(p, f, 9.6181291e-3f);
    p = fmaf(p, f, 5.5504109e-2f);
    p = fmaf(p, f, 2.4022651e-1f);
    p = fmaf(p, f, 6.9314718e-1f);
    p = fmaf(p, f, 1.0f);
    float sc = __int_as_float(((int)r + 127) << 23);
    return p * sc;
}

// ---------------- K/V split-bf16 precompute (once per layer) ----------------
// g_kc[h][p][n]: pair of K[n, h*64 + 2p..2p+1]
__global__ void convert_k_k(const float* __restrict__ Km) {
    int h = blockIdx.y;
    int n0 = blockIdx.x * 64;
    int t = threadIdx.x;
    int nl = t & 63, pg = t >> 6;
#pragma unroll
    for (int pi = 0; pi < 8; pi++) {
        int p = pg * 8 + pi;
        float2 a = *(const float2*)&Km[(size_t)(n0 + nl) * NHID + h * DKh + 2 * p];
        uint32_t hh, ll;
        split2(a.x, a.y, hh, ll);
        g_kc[((size_t)h * 32 + p) * Nn + n0 + nl] = make_uint2(hh, ll);
    }
}

// g_vc[h][kp][d]: pair of V[2kp, h*64+d], V[2kp+1, h*64+d]
__global__ void convert_v_k(const float* __restrict__ Vm) {
    int h = blockIdx.y;
    int kp0 = blockIdx.x * 32;
    int t = threadIdx.x;
    int d = t & 63, kg = t >> 6;
#pragma unroll
    for (int ki = 0; ki < 8; ki++) {
        int kp = kp0 + kg * 8 + ki;
        float v0 = Vm[(size_t)(2 * kp) * NHID + h * DKh + d];
        float v1 = Vm[(size_t)(2 * kp + 1) * NHID + h * DKh + d];
        uint32_t hh, ll;
        split2(v0, v1, hh, ll);
        g_vc[((size_t)h * (Nn / 2) + kp) * 64 + d] = make_uint2(hh, ll);
    }
}

// ---------------- dense split-bf16 GEMM (R8 structure: separate hi/lo) ----------------
#define BM 128
#define BN 128
#define BK 32
#define LDg 136

__device__ __forceinline__ void gemm_body(
    const float* __restrict__ A, int lda,
    const float* __restrict__ B, int ldb,
    float* __restrict__ C, int ldc,
    const float* __restrict__ bias,
    const float* __restrict__ add, float addScale,
    int K, int m0, int n0,
    uint32_t (*As_hi)[LDg], uint32_t (*As_lo)[LDg],
    uint32_t (*Bs_hi)[LDg], uint32_t (*Bs_lo)[LDg]) {
    int t = threadIdx.x;
    int lane = t & 31;
    int warp = t >> 5;
    int lq = lane & 3;
    int lr = lane >> 2;
    int wm = (warp >> 2) * 64;
    int wn = (warp & 3) * 32;

    float acc[4][4][4];
#pragma unroll
    for (int i = 0; i < 4; i++)
#pragma unroll
        for (int j = 0; j < 4; j++)
#pragma unroll
            for (int r = 0; r < 4; r++) acc[i][j][r] = 0.f;

    for (int k0 = 0; k0 < K; k0 += BK) {
        {
            int row = t >> 3, kq = t & 7;
#pragma unroll
            for (int p = 0; p < 4; p++) {
                int m = row + p * 32;
                float4 a = *(const float4*)&A[(size_t)(m0 + m) * lda + k0 + kq * 4];
                uint32_t h0, l0, h1, l1;
                split2(a.x, a.y, h0, l0);
                split2(a.z, a.w, h1, l1);
                As_hi[kq * 2 + 0][m] = h0; As_lo[kq * 2 + 0][m] = l0;
                As_hi[kq * 2 + 1][m] = h1; As_lo[kq * 2 + 1][m] = l1;
            }
        }
        {
#pragma unroll
            for (int p2 = 0; p2 < 2; p2++) {
                int tt = t + 256 * p2;
                int pr = tt >> 5, nq = tt & 31;
                float4 b0 = *(const float4*)&B[(size_t)(k0 + 2 * pr) * ldb + n0 + nq * 4];
                float4 b1 = *(const float4*)&B[(size_t)(k0 + 2 * pr + 1) * ldb + n0 + nq * 4];
                uint32_t h, l;
                split2(b0.x, b1.x, h, l); Bs_hi[pr][nq * 4 + 0] = h; Bs_lo[pr][nq * 4 + 0] = l;
                split2(b0.y, b1.y, h, l); Bs_hi[pr][nq * 4 + 1] = h; Bs_lo[pr][nq * 4 + 1] = l;
                split2(b0.z, b1.z, h, l); Bs_hi[pr][nq * 4 + 2] = h; Bs_lo[pr][nq * 4 + 2] = l;
                split2(b0.w, b1.w, h, l); Bs_hi[pr][nq * 4 + 3] = h; Bs_lo[pr][nq * 4 + 3] = l;
            }
        }
        __syncthreads();

#pragma unroll
        for (int kk = 0; kk < 2; kk++) {
            int p0 = kk * 8 + lq;
            uint32_t ah[4][4], al[4][4], bh[4][2], bl[4][2];
#pragma unroll
            for (int mi = 0; mi < 4; mi++) {
                int r = wm + mi * 16 + lr;
                ah[mi][0] = As_hi[p0][r];     al[mi][0] = As_lo[p0][r];
                ah[mi][1] = As_hi[p0][r + 8]; al[mi][1] = As_lo[p0][r + 8];
                ah[mi][2] = As_hi[p0 + 4][r];     al[mi][2] = As_lo[p0 + 4][r];
                ah[mi][3] = As_hi[p0 + 4][r + 8]; al[mi][3] = As_lo[p0 + 4][r + 8];
            }
#pragma unroll
            for (int ni = 0; ni < 4; ni++) {
                int c = wn + ni * 8 + lr;
                bh[ni][0] = Bs_hi[p0][c];     bl[ni][0] = Bs_lo[p0][c];
                bh[ni][1] = Bs_hi[p0 + 4][c]; bl[ni][1] = Bs_lo[p0 + 4][c];
            }
#pragma unroll
            for (int mi = 0; mi < 4; mi++)
#pragma unroll
                for (int ni = 0; ni < 4; ni++) {
                    mma_bf16(acc[mi][ni], ah[mi][0], ah[mi][1], ah[mi][2], ah[mi][3],
                             bh[ni][0], bh[ni][1]);
                    mma_bf16(acc[mi][ni], ah[mi][0], ah[mi][1], ah[mi][2], ah[mi][3],
                             bl[ni][0], bl[ni][1]);
                    mma_bf16(acc[mi][ni], al[mi][0], al[mi][1], al[mi][2], al[mi][3],
                             bh[ni][0], bh[ni][1]);
                }
        }
        __syncthreads();
    }

#pragma unroll
    for (int mi = 0; mi < 4; mi++) {
        int r0 = m0 + wm + mi * 16 + lr;
        int r1 = r0 + 8;
#pragma unroll
        for (int ni = 0; ni < 4; ni++) {
            int c0 = n0 + wn + ni * 8 + lq * 2;
            int c1 = c0 + 1;
            float v00 = acc[mi][ni][0];
            float v01 = acc[mi][ni][1];
            float v10 = acc[mi][ni][2];
            float v11 = acc[mi][ni][3];
            if (bias) { v00 += bias[c0]; v01 += bias[c1]; v10 += bias[c0]; v11 += bias[c1]; }
            if (add) {
                v00 += addScale * add[(size_t)r0 * ldc + c0];
                v01 += addScale * add[(size_t)r0 * ldc + c1];
                v10 += addScale * add[(size_t)r1 * ldc + c0];
                v11 += addScale * add[(size_t)r1 * ldc + c1];
            }
            C[(size_t)r0 * ldc + c0] = v00;
            C[(size_t)r0 * ldc + c1] = v01;
            C[(size_t)r1 * ldc + c0] = v10;
            C[(size_t)r1 * ldc + c1] = v11;
        }
    }
}

__global__ __launch_bounds__(256) void tc_gemm(
    const float* __restrict__ A, int lda,
    const float* __restrict__ B, int ldb,
    float* __restrict__ C, int ldc,
    const float* __restrict__ bias,
    const float* __restrict__ add, float addScale,
    int K) {
    __shared__ uint32_t As_hi[16][LDg], As_lo[16][LDg];
    __shared__ uint32_t Bs_hi[16][LDg], Bs_lo[16][LDg];
    gemm_body(A, lda, B, ldb, C, ldc, bias, add, addScale, K,
              blockIdx.y * BM, blockIdx.x * BN, As_hi, As_lo, Bs_hi, Bs_lo);
}

__global__ __launch_bounds__(256) void tc_gemm3(
    const float* __restrict__ A, int lda,
    const float* __restrict__ B0, const float* __restrict__ B1, const float* __restrict__ B2,
    int ldb,
    float* __restrict__ C0, float* __restrict__ C1, float* __restrict__ C2,
    int ldc,
    const float* __restrict__ bias0, const float* __restrict__ bias1, const float* __restrict__ bias2,
    int K) {
    __shared__ uint32_t As_hi[16][LDg], As_lo[16][LDg];
    __shared__ uint32_t Bs_hi[16][LDg], Bs_lo[16][LDg];
    int z = blockIdx.z;
    const float* B = (z == 0) ? B0 : (z == 1) ? B1 : B2;
    float* C = (z == 0) ? C0 : (z == 1) ? C1 : C2;
    const float* bias = (z == 0) ? bias0 : (z == 1) ? bias1 : bias2;
    gemm_body(A, lda, B, ldb, C, ldc, bias, nullptr, 0.f, K,
              blockIdx.y * BM, blockIdx.x * BN, As_hi, As_lo, Bs_hi, Bs_lo);
}

// ---------------- fused flash attention v5 ----------------
// Grid: (32 row-blocks, 8 heads). Block: 256 threads (8 warps x 16 rows = 128 rows).
// K/V pre-split in gmem (uint2); loop = pure copy + MMA. Register P, register prefetch.
#define FBC 64
#define KLD2 72   // uint2 stride -> 2*72 = 144 ≡ 16 mod 128 words: conflict-free fragment loads
#define QLD 132   // Q staging stride (floats)

#define U2_K 0
#define U2_V (32 * KLD2)
#define FLASH_U2 (64 * KLD2)   // 4608 uint2 = 36864 bytes

__global__ __launch_bounds__(256) void flash_k(
    const float* __restrict__ Q, const float* __restrict__ GV,
    float* __restrict__ CTX) {
    extern __shared__ uint2 sm2[];
    uint2* K2 = sm2 + U2_K;
    uint2* V2 = sm2 + U2_V;
    float* Qst = (float*)sm2;   // [64 d][QLD floats] = 33792 B, overlays K/V pre-loop

    const int t = threadIdx.x, lane = t & 31, warp = t >> 5;
    const int lq = lane & 3, lr = lane >> 2;
    const int h = blockIdx.y;
    const int r0 = blockIdx.x * 128;
    const int wr0 = warp * 16 + lr;

    // ---- stage Q into Qst[d][row]
    {
        int row = t >> 1;
        int dbase = (t & 1) * 32;
        const float* src = Q + (size_t)(r0 + row) * NHID + h * DKh + dbase;
#pragma unroll
        for (int i = 0; i < 8; i++) {
            float4 a = *(const float4*)(src + i * 4);
            Qst[(dbase + i * 4 + 0) * QLD + row] = a.x;
            Qst[(dbase + i * 4 + 1) * QLD + row] = a.y;
            Qst[(dbase + i * 4 + 2) * QLD + row] = a.z;
            Qst[(dbase + i * 4 + 3) * QLD + row] = a.w;
        }
    }
    __syncthreads();

    // ---- build Q fragments (scaled by 1/8), bf16 hi/lo
    uint32_t qh[4][4], ql[4][4];
#pragma unroll
    for (int s = 0; s < 4; s++) {
        int pa = s * 8 + lq;
#pragma unroll
        for (int half = 0; half < 2; half++) {
            int p = pa + half * 4;
            float x0 = Qst[(2 * p + 0) * QLD + wr0] * 0.125f;
            float x1 = Qst[(2 * p + 1) * QLD + wr0] * 0.125f;
            float y0 = Qst[(2 * p + 0) * QLD + wr0 + 8] * 0.125f;
            float y1 = Qst[(2 * p + 1) * QLD + wr0 + 8] * 0.125f;
            split2(x0, x1, qh[s][half * 2 + 0], ql[s][half * 2 + 0]);
            split2(y0, y1, qh[s][half * 2 + 1], ql[s][half * 2 + 1]);
        }
    }
    __syncthreads();

    float oacc[8][4];
#pragma unroll
    for (int ni = 0; ni < 8; ni++)
#pragma unroll
        for (int r = 0; r < 4; r++) oacc[ni][r] = 0.f;
    float m0 = -INFINITY, m1 = -INFINITY, l0 = 0.f, l1 = 0.f;

    // copy-index decomposition: idx = t + 256*i -> p = (t>>6)+4i, col = t&63
    const int pa0 = t >> 6, col = t & 63;
    const uint2* kcBase = g_kc + (size_t)h * 32 * Nn;
    const uint2* vcBase = g_vc + (size_t)h * (Nn / 2) * 64;

    // ---- prefetch tile 0
    uint2 kpref[8], vpref[8];
#pragma unroll
    for (int i = 0; i < 8; i++) {
        int p = pa0 + 4 * i;
        kpref[i] = kcBase[(size_t)p * Nn + col];
        vpref[i] = vcBase[(size_t)p * 64 + col];
    }

    for (int cb = 0; cb < Nn; cb += FBC) {
        // ---- store prefetched tile to smem
#pragma unroll
        for (int i = 0; i < 8; i++) {
            int p = pa0 + 4 * i;
            K2[p * KLD2 + col] = kpref[i];
            V2[p * KLD2 + col] = vpref[i];
        }
        __syncthreads();

        // ---- prefetch next tile
        if (cb + FBC < Nn) {
#pragma unroll
            for (int i = 0; i < 8; i++) {
                int p = pa0 + 4 * i;
                kpref[i] = kcBase[(size_t)p * Nn + (cb + FBC) + col];
                vpref[i] = vcBase[((size_t)(cb + FBC) / 2 + p) * 64 + col];
            }
        }

        // ---- S = (Q/8) @ K^T
        float sacc[8][4];
#pragma unroll
        for (int ni = 0; ni < 8; ni++)
#pragma unroll
            for (int r = 0; r < 4; r++) sacc[ni][r] = 0.f;
#pragma unroll
        for (int s = 0; s < 4; s++) {
            int p0 = s * 8 + lq;
#pragma unroll
            for (int ni = 0; ni < 8; ni++) {
                int c = ni * 8 + lr;
                uint2 B0 = K2[p0 * KLD2 + c];
                uint2 B1 = K2[(p0 + 4) * KLD2 + c];
                mma_bf16(sacc[ni], qh[s][0], qh[s][1], qh[s][2], qh[s][3], B0.x, B1.x);
                mma_bf16(sacc[ni], qh[s][0], qh[s][1], qh[s][2], qh[s][3], B0.y, B1.y);
                mma_bf16(sacc[ni], ql[s][0], ql[s][1], ql[s][2], ql[s][3], B0.x, B1.x);
            }
        }

        // ---- online softmax (register-resident)
        float bm0 = -INFINITY, bm1 = -INFINITY;
#pragma unroll
        for (int ni = 0; ni < 8; ni++) {
            bm0 = fmaxf(bm0, fmaxf(sacc[ni][0], sacc[ni][1]));
            bm1 = fmaxf(bm1, fmaxf(sacc[ni][2], sacc[ni][3]));
        }
        bm0 = fmaxf(bm0, __shfl_xor_sync(0xffffffffu, bm0, 1));
        bm0 = fmaxf(bm0, __shfl_xor_sync(0xffffffffu, bm0, 2));
        bm1 = fmaxf(bm1, __shfl_xor_sync(0xffffffffu, bm1, 1));
        bm1 = fmaxf(bm1, __shfl_xor_sync(0xffffffffu, bm1, 2));
        float mn0 = fmaxf(m0, bm0), mn1 = fmaxf(m1, bm1);
        float cf0 = fexp(m0 - mn0), cf1 = fexp(m1 - mn1);
        float s0 = 0.f, s1 = 0.f;
#pragma unroll
        for (int ni = 0; ni < 8; ni++) {
            sacc[ni][0] = fexp(sacc[ni][0] - mn0);
            sacc[ni][1] = fexp(sacc[ni][1] - mn0);
            sacc[ni][2] = fexp(sacc[ni][2] - mn1);
            sacc[ni][3] = fexp(sacc[ni][3] - mn1);
            s0 += sacc[ni][0] + sacc[ni][1];
            s1 += sacc[ni][2] + sacc[ni][3];
        }
        s0 += __shfl_xor_sync(0xffffffffu, s0, 1);
        s0 += __shfl_xor_sync(0xffffffffu, s0, 2);
        s1 += __shfl_xor_sync(0xffffffffu, s1, 1);
        s1 += __shfl_xor_sync(0xffffffffu, s1, 2);
        l0 = l0 * cf0 + s0;
        l1 = l1 * cf1 + s1;
        m0 = mn0; m1 = mn1;
#pragma unroll
        for (int ni = 0; ni < 8; ni++) {
            oacc[ni][0] *= cf0; oacc[ni][1] *= cf0;
            oacc[ni][2] *= cf1; oacc[ni][3] *= cf1;
        }

        // ---- O += P @ V with P straight from registers
#pragma unroll
        for (int s = 0; s < 4; s++) {
            uint32_t a0, a1, a2, a3, e0, e1, e2, e3;
            split2(sacc[2 * s][0],     sacc[2 * s][1],     a0, e0);
            split2(sacc[2 * s][2],     sacc[2 * s][3],     a1, e1);
            split2(sacc[2 * s + 1][0], sacc[2 * s + 1][1], a2, e2);
            split2(sacc[2 * s + 1][2], sacc[2 * s + 1][3], a3, e3);
            int p0 = s * 8 + lq;
#pragma unroll
            for (int ni = 0; ni < 8; ni++) {
                int c = ni * 8 + lr;
                uint2 B0 = V2[p0 * KLD2 + c];
                uint2 B1 = V2[(p0 + 4) * KLD2 + c];
                mma_bf16(oacc[ni], a0, a1, a2, a3, B0.x, B1.x);
                mma_bf16(oacc[ni], a0, a1, a2, a3, B0.y, B1.y);
                mma_bf16(oacc[ni], e0, e1, e2, e3, B0.x, B1.x);
            }
        }
        __syncthreads();
    }

    // ---- epilogue: ctx = 0.5*O/l + 0.5*gv
    float inv0 = 0.5f / l0, inv1 = 0.5f / l1;
#pragma unroll
    for (int ni = 0; ni < 8; ni++) {
        int c = ni * 8 + lq * 2;
        size_t o0 = (size_t)(r0 + wr0) * NHID + h * DKh + c;
        size_t o1 = (size_t)(r0 + wr0 + 8) * NHID + h * DKh + c;
        float2 gv0 = *(const float2*)&GV[o0];
        float2 gv1 = *(const float2*)&GV[o1];
        float2 w0, w1;
        w0.x = oacc[ni][0] * inv0 + 0.5f * gv0.x;
        w0.y = oacc[ni][1] * inv0 + 0.5f * gv0.y;
        w1.x = oacc[ni][2] * inv1 + 0.5f * gv1.x;
        w1.y = oacc[ni][3] * inv1 + 0.5f * gv1.y;
        *(float2*)&CTX[o0] = w0;
        *(float2*)&CTX[o1] = w1;
    }
}

// ---------------- layernorm + prelu ----------------
__global__ void ln_prelu_k(const float* __restrict__ in, float* __restrict__ out,
                           const float* __restrict__ g, const float* __restrict__ b,
                           const float* __restrict__ aptr) {
    int t = threadIdx.x;
    const float* row = in + (size_t)blockIdx.x * NHID;
    float x0 = row[t], x1 = row[t + 256];
    __shared__ float red[256];
    red[t] = x0 + x1; __syncthreads();
    for (int w = 128; w > 0; w >>= 1) { if (t < w) red[t] += red[t + w]; __syncthreads(); }
    float mu = red[0] * (1.0f / NHID);
    __syncthreads();
    float d0 = x0 - mu, d1 = x1 - mu;
    red[t] = d0 * d0 + d1 * d1; __syncthreads();
    for (int w = 128; w > 0; w >>= 1) { if (t < w) red[t] += red[t + w]; __syncthreads(); }
    float inv = rsqrtf(red[0] * (1.0f / NHID) + 1e-5f);
    float a = *aptr;
    float y0 = d0 * inv * g[t] + b[t];
    float y1 = d1 * inv * g[t + 256] + b[t + 256];
    float* orow = out + (size_t)blockIdx.x * NHID;
    orow[t] = (y0 >= 0.f) ? y0 : a * y0;
    orow[t + 256] = (y1 >= 0.f) ? y1 : a * y1;
}

// ---------------- classifier + log_softmax ----------------
__global__ void cls_k(const float* __restrict__ x, const float* __restrict__ w,
                      const float* __restrict__ bias, float* __restrict__ out) {
    __shared__ float xs[NHID];
    __shared__ float lg[NCLASS];
    int t = threadIdx.x;  // 128
    const float* row = x + (size_t)blockIdx.x * NHID;
    for (int i = t; i < NHID; i += 128) xs[i] = row[i];
    __syncthreads();
    if (t < NCLASS) {
        float s = bias[t];
        for (int k = 0; k < NHID; k++) s += xs[k] * w[k * NCLASS + t];
        lg[t] = s;
    }
    __syncthreads();
    if (t < NCLASS) {
        float mx = -INFINITY;
        for (int c = 0; c < NCLASS; c++) mx = fmaxf(mx, lg[c]);
        float sum = 0.f;
        for (int c = 0; c < NCLASS; c++) sum += __expf(lg[c] - mx);
        out[(size_t)blockIdx.x * NCLASS + t] = lg[t] - mx - logf(sum);
    }
}

// ---------------- host launcher ----------------
extern "C" void kernel_launch(void* const* d_in, const int* in_sizes, int n_in,
                              void* d_out, int out_size) {
    const float* X0     = (const float*)d_in[0];
    const float* Hm     = (const float*)d_in[1];
    const float* w_feat = (const float*)d_in[2];
    const float* b_feat = (const float*)d_in[3];
    const float* Wq     = (const float*)d_in[4];
    const float* bq     = (const float*)d_in[5];
    const float* Wk     = (const float*)d_in[6];
    const float* bk     = (const float*)d_in[7];
    const float* Wv     = (const float*)d_in[8];
    const float* bv     = (const float*)d_in[9];
    const float* Wo     = (const float*)d_in[10];
    const float* bo     = (const float*)d_in[11];
    const float* ln_g   = (const float*)d_in[12];
    const float* ln_b   = (const float*)d_in[13];
    const float* prelu_a= (const float*)d_in[14];
    const float* w_cls  = (const float*)d_in[15];
    const float* b_cls  = (const float*)d_in[16];
    float* out = (float*)d_out;

    float *x_, *q_, *k_, *v_, *gv_, *ctx_, *pre_;
    cudaGetSymbolAddress((void**)&x_, g_x);
    cudaGetSymbolAddress((void**)&q_, g_q);
    cudaGetSymbolAddress((void**)&k_, g_k);
    cudaGetSymbolAddress((void**)&v_, g_v);
    cudaGetSymbolAddress((void**)&gv_, g_gv);
    cudaGetSymbolAddress((void**)&ctx_, g_ctx);
    cudaGetSymbolAddress((void**)&pre_, g_pre);

    const int flashSmem = FLASH_U2 * 8;   // 36864 bytes
    cudaFuncSetAttribute(flash_k, cudaFuncAttributeMaxDynamicSharedMemorySize, flashSmem);

    row_sums_k<<<Nn, 256>>>(Hm);
    col_part_k<<<dim3(Ee / 256, 32), 256>>>(Hm);
    finalize_deg_k<<<Nn / 256, 256>>>();
    rowlist_k<<<Nn / 8, 256>>>(Hm);
    collist_k<<<Ee / 256, 256>>>(Hm);

    dim3 gHid(NHID / BN, Nn / BM);

    tc_gemm<<<gHid, 256>>>(X0, NHID, w_feat, NHID, x_, NHID, b_feat, nullptr, 0.f, NHID);

    for (int i = 0; i < NLAYER; i++) {
        const float* Wqi = Wq + (size_t)i * NHID * NHID;
        const float* Wki = Wk + (size_t)i * NHID * NHID;
        const float* Wvi = Wv + (size_t)i * NHID * NHID;
        const float* Woi = Wo + (size_t)i * NHID * NHID;

        tc_gemm3<<<dim3(NHID / BN, Nn / BM, 3), 256>>>(
            x_, NHID, Wqi, Wki, Wvi, NHID, q_, k_, v_, NHID,
            bq + i * NHID, bk + i * NHID, bv + i * NHID, NHID);

        // precompute split-bf16 K / V for flash
        convert_k_k<<<dim3(Nn / 64, NHEAD), 256>>>(k_);
        convert_v_k<<<dim3(Nn / 2 / 32, NHEAD), 256>>>(v_);

        edge_gather_k<<<Ee, 128>>>(v_);
        node_gather_k<<<Nn, 128>>>();

        flash_k<<<dim3(32, 8), 256, flashSmem>>>(q_, gv_, ctx_);

        tc_gemm<<<gHid, 256>>>(ctx_, NHID, Woi, NHID, pre_, NHID, bo + i * NHID, x_, 1.f, NHID);

        ln_prelu_k<<<Nn, 256>>>(pre_, x_, ln_g + i * NHID, ln_b + i * NHID, prelu_a + i);
    }

    cls_k<<<Nn, 128>>>(x_, w_cls, b_cls, out);
}

// round 14
// speedup vs baseline: 1.0883x; 1.0883x over previous
#include <cuda_runtime.h>
#include <cuda_bf16.h>
#include <math.h>
#include <stdint.h>

#define Nn 4096
#define Ee 4096
#define NHID 512
#define NHEAD 8
#define DKh 64
#define NLAYER 4
#define NCLASS 16
#define CAP 128

// ---------------- scratch ----------------
__device__ float g_x[Nn * NHID];
__device__ float g_q[Nn * NHID];
__device__ float g_k[Nn * NHID];
__device__ float g_v[Nn * NHID];
__device__ float g_w[Ee * NHID];
__device__ float g_gv[Nn * NHID];
__device__ float g_ctx[Nn * NHID];
__device__ float g_pre[Nn * NHID];
__device__ float g_DV[Nn];
__device__ float g_DEpart[32 * Ee];
__device__ float g_dv2[Nn];
__device__ float g_invDE[Ee];
__device__ int   g_rowIdx[Nn * CAP];
__device__ int   g_rowCnt[Nn];
__device__ int   g_colIdx[Ee * CAP];
__device__ int   g_colCnt[Ee];

// ---------------- degrees ----------------
__global__ void row_sums_k(const float* __restrict__ H) {
    int t = threadIdx.x;
    const float* row = H + (size_t)blockIdx.x * Ee;
    float s = 0.f;
    for (int e = t; e < Ee; e += 256) s += row[e];
    __shared__ float red[256];
    red[t] = s; __syncthreads();
    for (int w = 128; w > 0; w >>= 1) { if (t < w) red[t] += red[t + w]; __syncthreads(); }
    if (t == 0) g_DV[blockIdx.x] = red[0];
}

__global__ void col_part_k(const float* __restrict__ H) {
    int e = blockIdx.x * 256 + threadIdx.x;
    int r0 = blockIdx.y * 128;
    float s = 0.f;
    for (int n = r0; n < r0 + 128; n++) s += H[(size_t)n * Ee + e];
    g_DEpart[blockIdx.y * Ee + e] = s;
}

__global__ void finalize_deg_k() {
    int i = blockIdx.x * 256 + threadIdx.x;
    if (i < Nn) g_dv2[i] = (i == 0) ? 1.0f : rsqrtf(g_DV[i]);
    if (i < Ee) {
        float s = 0.f;
        for (int p = 0; p < 32; p++) s += g_DEpart[p * Ee + i];
        g_invDE[i] = 1.0f / s;
    }
}

// ---------------- CSR build (deterministic) ----------------
__global__ void rowlist_k(const float* __restrict__ H) {
    int warp = threadIdx.x >> 5, lane = threadIdx.x & 31;
    int n = blockIdx.x * 8 + warp;
    const float* row = H + (size_t)n * Ee;
    int cnt = 0;
    for (int base = 0; base < Ee; base += 32) {
        float v = row[base + lane];
        unsigned mask = __ballot_sync(0xffffffffu, v != 0.f);
        int off = __popc(mask & ((1u << lane) - 1u));
        if (v != 0.f && cnt + off < CAP) g_rowIdx[n * CAP + cnt + off] = base + lane;
        cnt += __popc(mask);
    }
    if (lane == 0) g_rowCnt[n] = cnt < CAP ? cnt : CAP;
}

__global__ void collist_k(const float* __restrict__ H) {
    int e = blockIdx.x * 256 + threadIdx.x;
    int cnt = 0;
    for (int n = 0; n < Nn; n++) {
        if (H[(size_t)n * Ee + e] != 0.f) {
            if (cnt < CAP) g_colIdx[e * CAP + cnt] = n;
            cnt++;
        }
    }
    g_colCnt[e] = cnt < CAP ? cnt : CAP;
}

// ---------------- sparse gathers ----------------
__global__ void edge_gather_k(const float* __restrict__ v) {
    int e = blockIdx.x, t = threadIdx.x;   // 128 threads
    int cnt = g_colCnt[e];
    float inv = g_invDE[e];
    float4 acc = make_float4(0.f, 0.f, 0.f, 0.f);
    const int* lst = g_colIdx + e * CAP;
    for (int j = 0; j < cnt; j++) {
        int n = lst[j];
        float s = g_dv2[n];
        float4 x = *(const float4*)&v[(size_t)n * NHID + t * 4];
        acc.x += s * x.x; acc.y += s * x.y; acc.z += s * x.z; acc.w += s * x.w;
    }
    float4 r = make_float4(inv * acc.x, inv * acc.y, inv * acc.z, inv * acc.w);
    *(float4*)&g_w[(size_t)e * NHID + t * 4] = r;
}

__global__ void node_gather_k() {
    int n = blockIdx.x, t = threadIdx.x;   // 128 threads
    int cnt = g_rowCnt[n];
    float s = g_dv2[n];
    float4 acc = make_float4(0.f, 0.f, 0.f, 0.f);
    const int* lst = g_rowIdx + n * CAP;
    for (int j = 0; j < cnt; j++) {
        int e = lst[j];
        float4 x = *(const float4*)&g_w[(size_t)e * NHID + t * 4];
        acc.x += x.x; acc.y += x.y; acc.z += x.z; acc.w += x.w;
    }
    float4 r = make_float4(s * acc.x, s * acc.y, s * acc.z, s * acc.w);
    *(float4*)&g_gv[(size_t)n * NHID + t * 4] = r;
}

// ---------------- bf16 split helpers ----------------
__device__ __forceinline__ void split2(float x0, float x1, uint32_t& hi, uint32_t& lo) {
    uint32_t h;
    asm("cvt.rn.bf16x2.f32 %0, %1, %2;" : "=r"(h) : "f"(x1), "f"(x0));
    float h0 = __uint_as_float(h << 16);
    float h1 = __uint_as_float(h & 0xffff0000u);
    asm("cvt.rn.bf16x2.f32 %0, %1, %2;" : "=r"(lo) : "f"(x1 - h1), "f"(x0 - h0));
    hi = h;
}

__device__ __forceinline__ void mma_bf16(float c[4], uint32_t a0, uint32_t a1,
                                         uint32_t a2, uint32_t a3,
                                         uint32_t b0, uint32_t b1) {
    asm volatile(
        "mma.sync.aligned.m16n8k16.row.col.f32.bf16.bf16.f32 "
        "{%0,%1,%2,%3},{%4,%5,%6,%7},{%8,%9},{%0,%1,%2,%3};"
        : "+f"(c[0]), "+f"(c[1]), "+f"(c[2]), "+f"(c[3])
        : "r"(a0), "r"(a1), "r"(a2), "r"(a3), "r"(b0), "r"(b1));
}

// FMA-pipe exp for x <= 0. rel err ~1e-7.
__device__ __forceinline__ float fexp(float x) {
    float y = x * 1.44269504088896f;
    y = fmaxf(y, -126.f);
    float r = rintf(y);
    float f = y - r;
    float p = 1.5426461e-4f;
    p = fmaf(p, f, 1.3333558e-3f);
    p = fmaf(p, f, 9.6181291e-3f);
    p = fmaf(p, f, 5.5504109e-2f);
    p = fmaf(p, f, 2.4022651e-1f);
    p = fmaf(p, f, 6.9314718e-1f);
    p = fmaf(p, f, 1.0f);
    float sc = __int_as_float(((int)r + 127) << 23);
    return p * sc;
}

// ---------------- dense split-bf16 GEMM (128x128x32 tile) ----------------
#define BM 128
#define BN 128
#define BK 32
#define LDg 136

__device__ __forceinline__ void gemm_body(
    const float* __restrict__ A, int lda,
    const float* __restrict__ B, int ldb,
    float* __restrict__ C, int ldc,
    const float* __restrict__ bias,
    const float* __restrict__ add, float addScale,
    int K, int m0, int n0,
    uint32_t (*As_hi)[LDg], uint32_t (*As_lo)[LDg],
    uint32_t (*Bs_hi)[LDg], uint32_t (*Bs_lo)[LDg]) {
    int t = threadIdx.x;
    int lane = t & 31;
    int warp = t >> 5;
    int lq = lane & 3;
    int lr = lane >> 2;
    int wm = (warp >> 2) * 64;
    int wn = (warp & 3) * 32;

    float acc[4][4][4];
#pragma unroll
    for (int i = 0; i < 4; i++)
#pragma unroll
        for (int j = 0; j < 4; j++)
#pragma unroll
            for (int r = 0; r < 4; r++) acc[i][j][r] = 0.f;

    for (int k0 = 0; k0 < K; k0 += BK) {
        {
            int row = t >> 3, kq = t & 7;
#pragma unroll
            for (int p = 0; p < 4; p++) {
                int m = row + p * 32;
                float4 a = *(const float4*)&A[(size_t)(m0 + m) * lda + k0 + kq * 4];
                uint32_t h0, l0, h1, l1;
                split2(a.x, a.y, h0, l0);
                split2(a.z, a.w, h1, l1);
                As_hi[kq * 2 + 0][m] = h0; As_lo[kq * 2 + 0][m] = l0;
                As_hi[kq * 2 + 1][m] = h1; As_lo[kq * 2 + 1][m] = l1;
            }
        }
        {
#pragma unroll
            for (int p2 = 0; p2 < 2; p2++) {
                int tt = t + 256 * p2;
                int pr = tt >> 5, nq = tt & 31;
                float4 b0 = *(const float4*)&B[(size_t)(k0 + 2 * pr) * ldb + n0 + nq * 4];
                float4 b1 = *(const float4*)&B[(size_t)(k0 + 2 * pr + 1) * ldb + n0 + nq * 4];
                uint32_t h, l;
                split2(b0.x, b1.x, h, l); Bs_hi[pr][nq * 4 + 0] = h; Bs_lo[pr][nq * 4 + 0] = l;
                split2(b0.y, b1.y, h, l); Bs_hi[pr][nq * 4 + 1] = h; Bs_lo[pr][nq * 4 + 1] = l;
                split2(b0.z, b1.z, h, l); Bs_hi[pr][nq * 4 + 2] = h; Bs_lo[pr][nq * 4 + 2] = l;
                split2(b0.w, b1.w, h, l); Bs_hi[pr][nq * 4 + 3] = h; Bs_lo[pr][nq * 4 + 3] = l;
            }
        }
        __syncthreads();

#pragma unroll
        for (int kk = 0; kk < 2; kk++) {
            int p0 = kk * 8 + lq;
            uint32_t ah[4][4], al[4][4], bh[4][2], bl[4][2];
#pragma unroll
            for (int mi = 0; mi < 4; mi++) {
                int r = wm + mi * 16 + lr;
                ah[mi][0] = As_hi[p0][r];     al[mi][0] = As_lo[p0][r];
                ah[mi][1] = As_hi[p0][r + 8]; al[mi][1] = As_lo[p0][r + 8];
                ah[mi][2] = As_hi[p0 + 4][r];     al[mi][2] = As_lo[p0 + 4][r];
                ah[mi][3] = As_hi[p0 + 4][r + 8]; al[mi][3] = As_lo[p0 + 4][r + 8];
            }
#pragma unroll
            for (int ni = 0; ni < 4; ni++) {
                int c = wn + ni * 8 + lr;
                bh[ni][0] = Bs_hi[p0][c];     bl[ni][0] = Bs_lo[p0][c];
                bh[ni][1] = Bs_hi[p0 + 4][c]; bl[ni][1] = Bs_lo[p0 + 4][c];
            }
#pragma unroll
            for (int mi = 0; mi < 4; mi++)
#pragma unroll
                for (int ni = 0; ni < 4; ni++) {
                    mma_bf16(acc[mi][ni], ah[mi][0], ah[mi][1], ah[mi][2], ah[mi][3],
                             bh[ni][0], bh[ni][1]);
                    mma_bf16(acc[mi][ni], ah[mi][0], ah[mi][1], ah[mi][2], ah[mi][3],
                             bl[ni][0], bl[ni][1]);
                    mma_bf16(acc[mi][ni], al[mi][0], al[mi][1], al[mi][2], al[mi][3],
                             bh[ni][0], bh[ni][1]);
                }
        }
        __syncthreads();
    }

#pragma unroll
    for (int mi = 0; mi < 4; mi++) {
        int r0 = m0 + wm + mi * 16 + lr;
        int r1 = r0 + 8;
#pragma unroll
        for (int ni = 0; ni < 4; ni++) {
            int c0 = n0 + wn + ni * 8 + lq * 2;
            int c1 = c0 + 1;
            float v00 = acc[mi][ni][0];
            float v01 = acc[mi][ni][1];
            float v10 = acc[mi][ni][2];
            float v11 = acc[mi][ni][3];
            if (bias) { v00 += bias[c0]; v01 += bias[c1]; v10 += bias[c0]; v11 += bias[c1]; }
            if (add) {
                v00 += addScale * add[(size_t)r0 * ldc + c0];
                v01 += addScale * add[(size_t)r0 * ldc + c1];
                v10 += addScale * add[(size_t)r1 * ldc + c0];
                v11 += addScale * add[(size_t)r1 * ldc + c1];
            }
            C[(size_t)r0 * ldc + c0] = v00;
            C[(size_t)r0 * ldc + c1] = v01;
            C[(size_t)r1 * ldc + c0] = v10;
            C[(size_t)r1 * ldc + c1] = v11;
        }
    }
}

__global__ __launch_bounds__(256) void tc_gemm(
    const float* __restrict__ A, int lda,
    const float* __restrict__ B, int ldb,
    float* __restrict__ C, int ldc,
    const float* __restrict__ bias,
    const float* __restrict__ add, float addScale,
    int K) {
    __shared__ uint32_t As_hi[16][LDg], As_lo[16][LDg];
    __shared__ uint32_t Bs_hi[16][LDg], Bs_lo[16][LDg];
    gemm_body(A, lda, B, ldb, C, ldc, bias, add, addScale, K,
              blockIdx.y * BM, blockIdx.x * BN, As_hi, As_lo, Bs_hi, Bs_lo);
}

// batched QKV projection: z selects {Wq,Wk,Wv}
__global__ __launch_bounds__(256) void tc_gemm3(
    const float* __restrict__ A, int lda,
    const float* __restrict__ B0, const float* __restrict__ B1, const float* __restrict__ B2,
    int ldb,
    float* __restrict__ C0, float* __restrict__ C1, float* __restrict__ C2,
    int ldc,
    const float* __restrict__ bias0, const float* __restrict__ bias1, const float* __restrict__ bias2,
    int K) {
    __shared__ uint32_t As_hi[16][LDg], As_lo[16][LDg];
    __shared__ uint32_t Bs_hi[16][LDg], Bs_lo[16][LDg];
    int z = blockIdx.z;
    const float* B = (z == 0) ? B0 : (z == 1) ? B1 : B2;
    float* C = (z == 0) ? C0 : (z == 1) ? C1 : C2;
    const float* bias = (z == 0) ? bias0 : (z == 1) ? bias1 : bias2;
    gemm_body(A, lda, B, ldb, C, ldc, bias, nullptr, 0.f, K,
              blockIdx.y * BM, blockIdx.x * BN, As_hi, As_lo, Bs_hi, Bs_lo);
}

// ---------------- fused flash attention v6 ----------------
// Grid: (32 row-blocks, 8 heads). Block: 256 threads (8 warps x 16 rows = 128 rows).
// R8 structure; no register prefetch; 2 CTAs/SM (regs ~120 < 128, no spill).
#define FBC 64
#define KLD 72   // stride (words) for K/V pair arrays [32][72]
#define QLD 132  // Q staging stride (floats)

#define OFF_KHI 0
#define OFF_KLO (OFF_KHI + 32 * KLD)
#define OFF_VHI (OFF_KLO + 32 * KLD)
#define OFF_VLO (OFF_VHI + 32 * KLD)
#define FLASH_WORDS (OFF_VLO + 32 * KLD)

__global__ __launch_bounds__(256, 2) void flash_k(
    const float* __restrict__ Q, const float* __restrict__ Km,
    const float* __restrict__ Vm, const float* __restrict__ GV,
    float* __restrict__ CTX) {
    extern __shared__ uint32_t sm[];
    uint32_t* Khi = sm + OFF_KHI;
    uint32_t* Klo = sm + OFF_KLO;
    uint32_t* Vhi = sm + OFF_VHI;
    uint32_t* Vlo = sm + OFF_VLO;
    float* Qst = (float*)sm;   // [64][QLD], overlays K/V region pre-loop

    const int t = threadIdx.x, lane = t & 31, warp = t >> 5;
    const int lq = lane & 3, lr = lane >> 2;
    const int h = blockIdx.y;
    const int r0 = blockIdx.x * 128;
    const int wr0 = warp * 16 + lr;

    // ---- stage Q into Qst[d][row]
    {
        int row = t >> 1;
        int dbase = (t & 1) * 32;
        const float* src = Q + (size_t)(r0 + row) * NHID + h * DKh + dbase;
#pragma unroll
        for (int i = 0; i < 8; i++) {
            float4 a = *(const float4*)(src + i * 4);
            Qst[(dbase + i * 4 + 0) * QLD + row] = a.x;
            Qst[(dbase + i * 4 + 1) * QLD + row] = a.y;
            Qst[(dbase + i * 4 + 2) * QLD + row] = a.z;
            Qst[(dbase + i * 4 + 3) * QLD + row] = a.w;
        }
    }
    __syncthreads();

    // ---- build Q fragments (scaled by 1/8), bf16 hi/lo
    uint32_t qh[4][4], ql[4][4];
#pragma unroll
    for (int s = 0; s < 4; s++) {
        int pa = s * 8 + lq;
#pragma unroll
        for (int half = 0; half < 2; half++) {
            int p = pa + half * 4;
            float x0 = Qst[(2 * p + 0) * QLD + wr0] * 0.125f;
            float x1 = Qst[(2 * p + 1) * QLD + wr0] * 0.125f;
            float y0 = Qst[(2 * p + 0) * QLD + wr0 + 8] * 0.125f;
            float y1 = Qst[(2 * p + 1) * QLD + wr0 + 8] * 0.125f;
            split2(x0, x1, qh[s][half * 2 + 0], ql[s][half * 2 + 0]);
            split2(y0, y1, qh[s][half * 2 + 1], ql[s][half * 2 + 1]);
        }
    }
    __syncthreads();

    float oacc[8][4];
#pragma unroll
    for (int ni = 0; ni < 8; ni++)
#pragma unroll
        for (int r = 0; r < 4; r++) oacc[ni][r] = 0.f;
    float m0 = -INFINITY, m1 = -INFINITY, l0 = 0.f, l1 = 0.f;

    const int key = t & 63, dbase2 = (t >> 6) * 16;

    for (int cb = 0; cb < Nn; cb += FBC) {
        // ---- load K (pairs along d) and V (pairs along key) directly to smem
        {
            const float* kp = Km + (size_t)(cb + key) * NHID + h * DKh + dbase2;
#pragma unroll
            for (int i = 0; i < 4; i++) {
                float4 a = *(const float4*)(kp + i * 4);
                int p = (dbase2 + i * 4) >> 1;
                uint32_t h0, lo0, h1, lo1;
                split2(a.x, a.y, h0, lo0);
                split2(a.z, a.w, h1, lo1);
                Khi[(p + 0) * KLD + key] = h0; Klo[(p + 0) * KLD + key] = lo0;
                Khi[(p + 1) * KLD + key] = h1; Klo[(p + 1) * KLD + key] = lo1;
            }
#pragma unroll
            for (int p2 = 0; p2 < 2; p2++) {
                int tt = t + 256 * p2;
                int kp2 = tt >> 4, dg = tt & 15;
                const float* v0p = Vm + (size_t)(cb + 2 * kp2) * NHID + h * DKh + dg * 4;
                float4 v0 = *(const float4*)v0p;
                float4 v1 = *(const float4*)(v0p + NHID);
                uint32_t hh, ll;
                split2(v0.x, v1.x, hh, ll); Vhi[kp2 * KLD + dg * 4 + 0] = hh; Vlo[kp2 * KLD + dg * 4 + 0] = ll;
                split2(v0.y, v1.y, hh, ll); Vhi[kp2 * KLD + dg * 4 + 1] = hh; Vlo[kp2 * KLD + dg * 4 + 1] = ll;
                split2(v0.z, v1.z, hh, ll); Vhi[kp2 * KLD + dg * 4 + 2] = hh; Vlo[kp2 * KLD + dg * 4 + 2] = ll;
                split2(v0.w, v1.w, hh, ll); Vhi[kp2 * KLD + dg * 4 + 3] = hh; Vlo[kp2 * KLD + dg * 4 + 3] = ll;
            }
        }
        __syncthreads();

        // ---- S = (Q/8) @ K^T
        float sacc[8][4];
#pragma unroll
        for (int ni = 0; ni < 8; ni++)
#pragma unroll
            for (int r = 0; r < 4; r++) sacc[ni][r] = 0.f;
#pragma unroll
        for (int s = 0; s < 4; s++) {
            int p0 = s * 8 + lq;
#pragma unroll
            for (int ni = 0; ni < 8; ni++) {
                int c = ni * 8 + lr;
                uint32_t b0 = Khi[p0 * KLD + c], b1 = Khi[(p0 + 4) * KLD + c];
                uint32_t c0 = Klo[p0 * KLD + c], c1 = Klo[(p0 + 4) * KLD + c];
                mma_bf16(sacc[ni], qh[s][0], qh[s][1], qh[s][2], qh[s][3], b0, b1);
                mma_bf16(sacc[ni], qh[s][0], qh[s][1], qh[s][2], qh[s][3], c0, c1);
                mma_bf16(sacc[ni], ql[s][0], ql[s][1], ql[s][2], ql[s][3], b0, b1);
            }
        }

        // ---- online softmax (register-resident)
        float bm0 = -INFINITY, bm1 = -INFINITY;
#pragma unroll
        for (int ni = 0; ni < 8; ni++) {
            bm0 = fmaxf(bm0, fmaxf(sacc[ni][0], sacc[ni][1]));
            bm1 = fmaxf(bm1, fmaxf(sacc[ni][2], sacc[ni][3]));
        }
        bm0 = fmaxf(bm0, __shfl_xor_sync(0xffffffffu, bm0, 1));
        bm0 = fmaxf(bm0, __shfl_xor_sync(0xffffffffu, bm0, 2));
        bm1 = fmaxf(bm1, __shfl_xor_sync(0xffffffffu, bm1, 1));
        bm1 = fmaxf(bm1, __shfl_xor_sync(0xffffffffu, bm1, 2));
        float mn0 = fmaxf(m0, bm0), mn1 = fmaxf(m1, bm1);
        float cf0 = fexp(m0 - mn0), cf1 = fexp(m1 - mn1);
        float s0 = 0.f, s1 = 0.f;
#pragma unroll
        for (int ni = 0; ni < 8; ni++) {
            sacc[ni][0] = fexp(sacc[ni][0] - mn0);
            sacc[ni][1] = fexp(sacc[ni][1] - mn0);
            sacc[ni][2] = fexp(sacc[ni][2] - mn1);
            sacc[ni][3] = fexp(sacc[ni][3] - mn1);
            s0 += sacc[ni][0] + sacc[ni][1];
            s1 += sacc[ni][2] + sacc[ni][3];
        }
        s0 += __shfl_xor_sync(0xffffffffu, s0, 1);
        s0 += __shfl_xor_sync(0xffffffffu, s0, 2);
        s1 += __shfl_xor_sync(0xffffffffu, s1, 1);
        s1 += __shfl_xor_sync(0xffffffffu, s1, 2);
        l0 = l0 * cf0 + s0;
        l1 = l1 * cf1 + s1;
        m0 = mn0; m1 = mn1;
#pragma unroll
        for (int ni = 0; ni < 8; ni++) {
            oacc[ni][0] *= cf0; oacc[ni][1] *= cf0;
            oacc[ni][2] *= cf1; oacc[ni][3] *= cf1;
        }

        // ---- O += P @ V with P straight from registers
#pragma unroll
        for (int s = 0; s < 4; s++) {
            uint32_t a0, a1, a2, a3, e0, e1, e2, e3;
            split2(sacc[2 * s][0],     sacc[2 * s][1],     a0, e0);
            split2(sacc[2 * s][2],     sacc[2 * s][3],     a1, e1);
            split2(sacc[2 * s + 1][0], sacc[2 * s + 1][1], a2, e2);
            split2(sacc[2 * s + 1][2], sacc[2 * s + 1][3], a3, e3);
            int p0 = s * 8 + lq;
#pragma unroll
            for (int ni = 0; ni < 8; ni++) {
                int c = ni * 8 + lr;
                uint32_t b0 = Vhi[p0 * KLD + c], b1 = Vhi[(p0 + 4) * KLD + c];
                uint32_t c0 = Vlo[p0 * KLD + c], c1 = Vlo[(p0 + 4) * KLD + c];
                mma_bf16(oacc[ni], a0, a1, a2, a3, b0, b1);
                mma_bf16(oacc[ni], a0, a1, a2, a3, c0, c1);
                mma_bf16(oacc[ni], e0, e1, e2, e3, b0, b1);
            }
        }
        __syncthreads();
    }

    // ---- epilogue: ctx = 0.5*O/l + 0.5*gv
    float inv0 = 0.5f / l0, inv1 = 0.5f / l1;
#pragma unroll
    for (int ni = 0; ni < 8; ni++) {
        int c = ni * 8 + lq * 2;
        size_t o0 = (size_t)(r0 + wr0) * NHID + h * DKh + c;
        size_t o1 = (size_t)(r0 + wr0 + 8) * NHID + h * DKh + c;
        float2 gv0 = *(const float2*)&GV[o0];
        float2 gv1 = *(const float2*)&GV[o1];
        float2 w0, w1;
        w0.x = oacc[ni][0] * inv0 + 0.5f * gv0.x;
        w0.y = oacc[ni][1] * inv0 + 0.5f * gv0.y;
        w1.x = oacc[ni][2] * inv1 + 0.5f * gv1.x;
        w1.y = oacc[ni][3] * inv1 + 0.5f * gv1.y;
        *(float2*)&CTX[o0] = w0;
        *(float2*)&CTX[o1] = w1;
    }
}

// ---------------- layernorm + prelu ----------------
__global__ void ln_prelu_k(const float* __restrict__ in, float* __restrict__ out,
                           const float* __restrict__ g, const float* __restrict__ b,
                           const float* __restrict__ aptr) {
    int t = threadIdx.x;
    const float* row = in + (size_t)blockIdx.x * NHID;
    float x0 = row[t], x1 = row[t + 256];
    __shared__ float red[256];
    red[t] = x0 + x1; __syncthreads();
    for (int w = 128; w > 0; w >>= 1) { if (t < w) red[t] += red[t + w]; __syncthreads(); }
    float mu = red[0] * (1.0f / NHID);
    __syncthreads();
    float d0 = x0 - mu, d1 = x1 - mu;
    red[t] = d0 * d0 + d1 * d1; __syncthreads();
    for (int w = 128; w > 0; w >>= 1) { if (t < w) red[t] += red[t + w]; __syncthreads(); }
    float inv = rsqrtf(red[0] * (1.0f / NHID) + 1e-5f);
    float a = *aptr;
    float y0 = d0 * inv * g[t] + b[t];
    float y1 = d1 * inv * g[t + 256] + b[t + 256];
    float* orow = out + (size_t)blockIdx.x * NHID;
    orow[t] = (y0 >= 0.f) ? y0 : a * y0;
    orow[t + 256] = (y1 >= 0.f) ? y1 : a * y1;
}

// ---------------- classifier + log_softmax ----------------
__global__ void cls_k(const float* __restrict__ x, const float* __restrict__ w,
                      const float* __restrict__ bias, float* __restrict__ out) {
    __shared__ float xs[NHID];
    __shared__ float lg[NCLASS];
    int t = threadIdx.x;  // 128
    const float* row = x + (size_t)blockIdx.x * NHID;
    for (int i = t; i < NHID; i += 128) xs[i] = row[i];
    __syncthreads();
    if (t < NCLASS) {
        float s = bias[t];
        for (int k = 0; k < NHID; k++) s += xs[k] * w[k * NCLASS + t];
        lg[t] = s;
    }
    __syncthreads();
    if (t < NCLASS) {
        float mx = -INFINITY;
        for (int c = 0; c < NCLASS; c++) mx = fmaxf(mx, lg[c]);
        float sum = 0.f;
        for (int c = 0; c < NCLASS; c++) sum += __expf(lg[c] - mx);
        out[(size_t)blockIdx.x * NCLASS + t] = lg[t] - mx - logf(sum);
    }
}

// ---------------- host launcher ----------------
extern "C" void kernel_launch(void* const* d_in, const int* in_sizes, int n_in,
                              void* d_out, int out_size) {
    const float* X0     = (const float*)d_in[0];
    const float* Hm     = (const float*)d_in[1];
    const float* w_feat = (const float*)d_in[2];
    const float* b_feat = (const float*)d_in[3];
    const float* Wq     = (const float*)d_in[4];
    const float* bq     = (const float*)d_in[5];
    const float* Wk     = (const float*)d_in[6];
    const float* bk     = (const float*)d_in[7];
    const float* Wv     = (const float*)d_in[8];
    const float* bv     = (const float*)d_in[9];
    const float* Wo     = (const float*)d_in[10];
    const float* bo     = (const float*)d_in[11];
    const float* ln_g   = (const float*)d_in[12];
    const float* ln_b   = (const float*)d_in[13];
    const float* prelu_a= (const float*)d_in[14];
    const float* w_cls  = (const float*)d_in[15];
    const float* b_cls  = (const float*)d_in[16];
    float* out = (float*)d_out;

    float *x_, *q_, *k_, *v_, *gv_, *ctx_, *pre_;
    cudaGetSymbolAddress((void**)&x_, g_x);
    cudaGetSymbolAddress((void**)&q_, g_q);
    cudaGetSymbolAddress((void**)&k_, g_k);
    cudaGetSymbolAddress((void**)&v_, g_v);
    cudaGetSymbolAddress((void**)&gv_, g_gv);
    cudaGetSymbolAddress((void**)&ctx_, g_ctx);
    cudaGetSymbolAddress((void**)&pre_, g_pre);

    const int flashSmem = FLASH_WORDS * 4;   // 36864 bytes
    cudaFuncSetAttribute(flash_k, cudaFuncAttributeMaxDynamicSharedMemorySize, flashSmem);

    row_sums_k<<<Nn, 256>>>(Hm);
    col_part_k<<<dim3(Ee / 256, 32), 256>>>(Hm);
    finalize_deg_k<<<Nn / 256, 256>>>();
    rowlist_k<<<Nn / 8, 256>>>(Hm);
    collist_k<<<Ee / 256, 256>>>(Hm);

    dim3 gHid(NHID / BN, Nn / BM);

    tc_gemm<<<gHid, 256>>>(X0, NHID, w_feat, NHID, x_, NHID, b_feat, nullptr, 0.f, NHID);

    for (int i = 0; i < NLAYER; i++) {
        const float* Wqi = Wq + (size_t)i * NHID * NHID;
        const float* Wki = Wk + (size_t)i * NHID * NHID;
        const float* Wvi = Wv + (size_t)i * NHID * NHID;
        const float* Woi = Wo + (size_t)i * NHID * NHID;

        tc_gemm3<<<dim3(NHID / BN, Nn / BM, 3), 256>>>(
            x_, NHID, Wqi, Wki, Wvi, NHID, q_, k_, v_, NHID,
            bq + i * NHID, bk + i * NHID, bv + i * NHID, NHID);

        edge_gather_k<<<Ee, 128>>>(v_);
        node_gather_k<<<Nn, 128>>>();

        flash_k<<<dim3(32, 8), 256, flashSmem>>>(q_, k_, v_, gv_, ctx_);

        tc_gemm<<<gHid, 256>>>(ctx_, NHID, Woi, NHID, pre_, NHID, bo + i * NHID, x_, 1.f, NHID);

        ln_prelu_k<<<Nn, 256>>>(pre_, x_, ln_g + i * NHID, ln_b + i * NHID, prelu_a + i);
    }

    cls_k<<<Nn, 128>>>(x_, w_cls, b_cls, out);
}